// round 2
// baseline (speedup 1.0000x reference)
#include <cuda_runtime.h>

// PositionEmbeddingEncoder: 1M points, 8 grid levels (2^d per axis),
// gather 8-float embedding row per level, concat -> [N, 64] fp32.
//
// inputs (metadata order): x [N*3] f32, w1..w8 [8^d * 8] f32
// output: [N, 64] f32

#define SIZE_F     256.0f
#define HALF_SIZE  128.0f
#define EMBED_DIM  8
#define N_DEPTH    8

__global__ __launch_bounds__(256)
void pee_kernel(const float* __restrict__ x,
                const float* __restrict__ w1,
                const float* __restrict__ w2,
                const float* __restrict__ w3,
                const float* __restrict__ w4,
                const float* __restrict__ w5,
                const float* __restrict__ w6,
                const float* __restrict__ w7,
                const float* __restrict__ w8,
                float* __restrict__ out,
                int n)
{
    int i = blockIdx.x * blockDim.x + threadIdx.x;
    if (i >= n) return;

    // scale to [0,1): matches (x + SIZE/2) / SIZE in fp32
    float sx = (x[3 * i + 0] + HALF_SIZE) * (1.0f / SIZE_F);
    float sy = (x[3 * i + 1] + HALF_SIZE) * (1.0f / SIZE_F);
    float sz = (x[3 * i + 2] + HALF_SIZE) * (1.0f / SIZE_F);

    const float* tables[N_DEPTH] = { w1, w2, w3, w4, w5, w6, w7, w8 };

    float4* orow = (float4*)(out + (size_t)i * (N_DEPTH * EMBED_DIM));

#pragma unroll
    for (int d = 1; d <= N_DEPTH; d++) {
        const int   gi = 1 << d;
        const float gf = (float)gi;

        int gx = (int)floorf(sx * gf);
        int gy = (int)floorf(sy * gf);
        int gz = (int)floorf(sz * gf);
        gx = min(max(gx, 0), gi - 1);
        gy = min(max(gy, 0), gi - 1);
        gz = min(max(gz, 0), gi - 1);

        unsigned int flat = (unsigned int)gx
                          + ((unsigned int)gy << d)
                          + ((unsigned int)gz << (2 * d));

        const float4* row = (const float4*)(tables[d - 1] + (size_t)flat * EMBED_DIM);
        float4 a = __ldg(row + 0);
        float4 b = __ldg(row + 1);

        orow[(d - 1) * 2 + 0] = a;
        orow[(d - 1) * 2 + 1] = b;
    }
}

extern "C" void kernel_launch(void* const* d_in, const int* in_sizes, int n_in,
                              void* d_out, int out_size)
{
    const float* x  = (const float*)d_in[0];
    const float* w1 = (const float*)d_in[1];
    const float* w2 = (const float*)d_in[2];
    const float* w3 = (const float*)d_in[3];
    const float* w4 = (const float*)d_in[4];
    const float* w5 = (const float*)d_in[5];
    const float* w6 = (const float*)d_in[6];
    const float* w7 = (const float*)d_in[7];
    const float* w8 = (const float*)d_in[8];
    float* out = (float*)d_out;

    int n = in_sizes[0] / 3;
    int threads = 256;
    int blocks = (n + threads - 1) / threads;
    pee_kernel<<<blocks, threads>>>(x, w1, w2, w3, w4, w5, w6, w7, w8, out, n);
}